// round 16
// baseline (speedup 1.0000x reference)
#include <cuda_runtime.h>
#include <cuda_fp16.h>

#define H 512
#define W 512
#define C 3
#define HW (H * W)
#define CHW (C * H * W)
#define N_IT 30

static constexpr float TAU      = (float)0.01;
static constexpr float LAM2     = (float)0.15;
static constexpr float RHO      = (float)1.99;
static constexpr float SIGMA    = (float)(1.0 / 0.01 / 72.0);
static constexpr float TAU_LAM1 = (float)(0.01 * 0.1);
static constexpr float INV_1PT  = (float)(1.0 / 1.01);

// Ping-pong scratch planes (parity-indexed; no cudaMalloc anywhere)
__device__ float  g_u0[2][CHW], g_u1[2][CHW], g_u2[2][CHW], g_u3[2][CHW];
__device__ float  g_px[2][CHW];
__device__ __half g_p0[2][CHW], g_p1[2][CHW];

__device__ __forceinline__ float4 ld4(const float* p) {
    return *reinterpret_cast<const float4*>(p);
}
__device__ __forceinline__ void st4(float* p, float a, float b, float c, float d) {
    *reinterpret_cast<float4*>(p) = make_float4(a, b, c, d);
}
__device__ __forceinline__ void hld4(const __half* p, float* o) {
    uint2 v = *reinterpret_cast<const uint2*>(p);
    float2 f0 = __half22float2(*reinterpret_cast<const __half2*>(&v.x));
    float2 f1 = __half22float2(*reinterpret_cast<const __half2*>(&v.y));
    o[0] = f0.x; o[1] = f0.y; o[2] = f1.x; o[3] = f1.y;
}
__device__ __forceinline__ float hld1(const __half* p) { return __half2float(*p); }
__device__ __forceinline__ void hst4(__half* p, float a, float b, float c, float d) {
    __half2 h0 = __floats2half2_rn(a, b);
    __half2 h1 = __floats2half2_rn(c, d);
    uint2 v;
    v.x = *reinterpret_cast<unsigned*>(&h0);
    v.y = *reinterpret_cast<unsigned*>(&h1);
    *reinterpret_cast<uint2*>(p) = v;
}

// ---------------------------------------------------------------------------
// Setup = init + trivial A_0: x2 = y, r2 = 0, u^(0)=0 (buf0), px_0 = y (buf0),
// p0_0 = p1_0 = 0 (buf0).
// ---------------------------------------------------------------------------
__global__ __launch_bounds__(256) void k_setup(const float* __restrict__ y,
                                               float* __restrict__ x2,
                                               float* __restrict__ r2f) {
    int t = blockIdx.x * blockDim.x + threadIdx.x;
    int idx = t * 4;
    float4 yv = ld4(y + idx);
    *reinterpret_cast<float4*>(x2 + idx)      = yv;
    *reinterpret_cast<float4*>(g_px[0] + idx) = yv;
    st4(r2f + 2 * idx,     0.f, 0.f, 0.f, 0.f);
    st4(r2f + 2 * idx + 4, 0.f, 0.f, 0.f, 0.f);
    hst4(g_p0[0] + idx, 0.f, 0.f, 0.f, 0.f);
    hst4(g_p1[0] + idx, 0.f, 0.f, 0.f, 0.f);
    st4(g_u0[0] + idx, 0.f, 0.f, 0.f, 0.f);
    st4(g_u1[0] + idx, 0.f, 0.f, 0.f, 0.f);
    st4(g_u2[0] + idx, 0.f, 0.f, 0.f, 0.f);
    st4(g_u3[0] + idx, 0.f, 0.f, 0.f, 0.f);
}

// ---------------------------------------------------------------------------
// B-step compute for one quad at global idx, reading parity-src planes.
// Bit-identical math to R15 phaseB. Results in nu0..nu3[4].
// ---------------------------------------------------------------------------
__device__ __forceinline__ void phaseB_compute(int idx, int src,
                                               float* nu0, float* nu1,
                                               float* nu2, float* nu3) {
    const float*  px  = g_px[src];
    const __half* p0p = g_p0[src];
    const __half* p1p = g_p1[src];

    int j0 = idx & (W - 1);
    int i  = (idx >> 9) & (H - 1);
    bool up = (i >= 1), down = (i + 1 < H);
    bool rowlast = (j0 + 4 == W), rowfirst = (j0 == 0);

    const float4 Z = make_float4(0, 0, 0, 0);
    float4 pxc = ld4(px + idx);
    float4 pxu = up   ? ld4(px + idx - W) : Z;
    float4 pxd = down ? ld4(px + idx + W) : Z;
    float pxl  = rowfirst ? 0.f : px[idx - 1];
    float pxr  = rowlast  ? 0.f : px[idx + 4];
    float pxdl = (down && !rowfirst) ? px[idx + W - 1] : 0.f;
    float pxdr = (down && !rowlast)  ? px[idx + W + 4] : 0.f;

    float p0w[5];
    p0w[0] = rowfirst ? 0.f : hld1(p0p + idx - 1);
    hld4(p0p + idx, p0w + 1);
    float p0ua[4] = {0, 0, 0, 0};
    if (up) hld4(p0p + idx - W, p0ua);
    float p1w[5];
    p1w[0] = rowfirst ? 0.f : hld1(p1p + idx - 1);
    hld4(p1p + idx, p1w + 1);
    float p1da[4] = {0, 0, 0, 0};
    if (down) hld4(p1p + idx + W, p1da);

    float pxa[6]  = {pxl, pxc.x, pxc.y, pxc.z, pxc.w, pxr};
    float pxda[6] = {pxdl, pxd.x, pxd.y, pxd.z, pxd.w, pxdr};
    float pxua[4] = {pxu.x, pxu.y, pxu.z, pxu.w};

    float4 u0c = ld4(g_u0[src] + idx);
    float4 u1c = ld4(g_u1[src] + idx);
    float4 u2c = ld4(g_u2[src] + idx);
    float4 u3c = ld4(g_u3[src] + idx);
    float uo0[4] = {u0c.x, u0c.y, u0c.z, u0c.w};
    float uo1[4] = {u1c.x, u1c.y, u1c.z, u1c.w};
    float uo2[4] = {u2c.x, u2c.y, u2c.z, u2c.w};
    float uo3[4] = {u3c.x, u3c.y, u3c.z, u3c.w};

#pragma unroll
    for (int k = 0; k < 4; ++k) {
        int kc = k + 1;
        bool lok = (k > 0) || !rowfirst;
        bool rok = (k < 3) || !rowlast;

        float q0c = (down ? (pxda[kc] - pxa[kc]) : 0.f) - p0w[k + 1];
        float q0u = up  ? ((pxa[kc] - pxua[k]) - p0ua[k]) : 0.f;
        float q0l = lok ? ((down ? (pxda[kc - 1] - pxa[kc - 1]) : 0.f) - p0w[k]) : 0.f;
        float q1c = (rok ? (pxa[kc + 1] - pxa[kc]) : 0.f) - p1w[k + 1];
        float q1l = lok ? ((pxa[kc] - pxa[kc - 1]) - p1w[k]) : 0.f;
        float q1d = down ? ((rok ? (pxda[kc + 1] - pxda[kc]) : 0.f) - p1da[k]) : 0.f;

        float e0 = q0c - q0u;
        float e1 = lok ? (q0c - q0l) : 0.f;
        float e2 = q1c - q1l;
        float e3 = down ? (q1d - q1c) : 0.f;

        float un0 = uo0[k] + SIGMA * e0;
        float un1 = uo1[k] + SIGMA * e1;
        float un2 = uo2[k] + SIGMA * e2;
        float un3 = uo3[k] + SIGMA * e3;

        float s  = un0 * un0 + un1 * un1 + un2 * un2 + un3 * un3;
        float im = fminf(LAM2 * rsqrtf(s), 1.0f);

        nu0[k] = uo0[k] + RHO * (un0 * im - uo0[k]);
        nu1[k] = uo1[k] + RHO * (un1 * im - uo1[k]);
        nu2[k] = uo2[k] + RHO * (un2 * im - uo2[k]);
        nu3[k] = uo3[k] + RHO * (un3 * im - uo3[k]);
    }
}

// smem u patch: 34 rows (gi0-1 .. gi0+32) x 72 cols (gj0-4 .. gj0+67)
#define SROWS 34
#define SCOLS 72

// ---------------------------------------------------------------------------
// Fused kernel F_it = B_{it-1} (tile+halo, into smem + dst planes) + A_it
// (tile, u from smem). src = (it-1)&1, dst = src^1.
// ---------------------------------------------------------------------------
__global__ __launch_bounds__(256) void k_F(int src,
                                           float* __restrict__ x2,
                                           float* __restrict__ r2f,
                                           const float* __restrict__ y) {
    __shared__ float su[4][SROWS][SCOLS];

    const int tid = threadIdx.x;
    const int bid = blockIdx.x;
    const int c   = bid >> 7;
    const int rem = bid & 127;
    const int bi  = rem >> 3;          // 0..15
    const int bj  = rem & 7;           // 0..7
    const int gi0 = bi * 32;
    const int gj0 = bj * 64;
    const int base = c * HW;
    const int dst = src ^ 1;

#if __CUDA_ARCH__ >= 900
    cudaGridDependencySynchronize();
#endif

    // ---- Stage B: u_new over 34 x 18-quads region -------------------------
    for (int q = tid; q < SROWS * 18; q += 256) {
        int r  = q / 18;
        int cq = q - r * 18;
        int gi = gi0 - 1 + r;
        int gj = gj0 - 4 + cq * 4;
        bool in = ((unsigned)gi < (unsigned)H) && ((unsigned)gj < (unsigned)W);

        float nu0[4] = {0, 0, 0, 0}, nu1[4] = {0, 0, 0, 0};
        float nu2[4] = {0, 0, 0, 0}, nu3[4] = {0, 0, 0, 0};
        if (in) {
            int idx = base + gi * W + gj;
            phaseB_compute(idx, src, nu0, nu1, nu2, nu3);
            // center quads also persist to global dst state
            if ((unsigned)(gi - gi0) < 32u && (unsigned)(gj - gj0) < 64u) {
                st4(g_u0[dst] + idx, nu0[0], nu0[1], nu0[2], nu0[3]);
                st4(g_u1[dst] + idx, nu1[0], nu1[1], nu1[2], nu1[3]);
                st4(g_u2[dst] + idx, nu2[0], nu2[1], nu2[2], nu2[3]);
                st4(g_u3[dst] + idx, nu3[0], nu3[1], nu3[2], nu3[3]);
            }
        }
        int sc = cq * 4;
#pragma unroll
        for (int k = 0; k < 4; ++k) {
            su[0][r][sc + k] = nu0[k];
            su[1][r][sc + k] = nu1[k];
            su[2][r][sc + k] = nu2[k];
            su[3][r][sc + k] = nu3[k];
        }
    }
    __syncthreads();

    // ---- Stage A: 2 row-stacked quads per thread, u from smem -------------
#pragma unroll
    for (int qi = 0; qi < 2; ++qi) {
        int ti = (tid >> 4) * 2 + qi;          // 0..31
        int tj = (tid & 15) * 4;               // 0..60
        int gi = gi0 + ti, gj = gj0 + tj;
        int idx = base + gi * W + gj;
        int sr = ti + 1;                        // smem row of global row gi
        int sc = tj + 4;                        // smem col of global col gj

        bool up = (gi >= 1), down = (gi + 1 < H);
        bool rowlast = (gj + 4 == W), rowfirst = (gj == 0);

        float u0c[4], u0u[4], u0d[4], u1c[5], u1u[5];
        float u2w[6], u3w[5], u3uw[5];
#pragma unroll
        for (int k = 0; k < 4; ++k) {
            u0c[k] = su[0][sr][sc + k];
            u0u[k] = su[0][sr - 1][sc + k];
            u0d[k] = su[0][sr + 1][sc + k];
            u1c[k] = su[1][sr][sc + k];
            u1u[k] = su[1][sr - 1][sc + k];
        }
        u1c[4] = su[1][sr][sc + 4];
        u1u[4] = su[1][sr - 1][sc + 4];
#pragma unroll
        for (int m = 0; m < 6; ++m) u2w[m] = su[2][sr][sc - 1 + m];
#pragma unroll
        for (int m = 0; m < 5; ++m) {
            u3w[m]  = su[3][sr][sc - 1 + m];
            u3uw[m] = su[3][sr - 1][sc - 1 + m];
        }

        float4 xo4 = ld4(x2 + idx);
        float4 y4  = ld4(y + idx);
        float4 rA  = ld4(r2f + 2 * idx);
        float4 rB  = ld4(r2f + 2 * idx + 4);
        float xoa[4] = {xo4.x, xo4.y, xo4.z, xo4.w};
        float ya[4]  = {y4.x, y4.y, y4.z, y4.w};
        float ro0[4] = {rA.x, rA.z, rB.x, rB.z};
        float ro1[4] = {rA.y, rA.w, rB.y, rB.w};

        float pxo[4], p0o[4], p1o[4], xno[4], rn0[4], rn1[4];
#pragma unroll
        for (int k = 0; k < 4; ++k) {
            bool lok = (k > 0) || !rowfirst;
            bool rok = (k < 3) || !rowlast;

            float t0c = TAU * (u0c[k] - (down ? u0d[k] : 0.f)
                               + (lok ? u1c[k] : 0.f) - (rok ? u1c[k + 1] : 0.f));
            float t1c = TAU * (u2w[k + 1] - (rok ? u2w[k + 2] : 0.f)
                               + (up ? u3uw[k + 1] : 0.f) - (down ? u3w[k + 1] : 0.f));
            float t0u = up ? TAU * (u0u[k] - u0c[k]
                                    + (lok ? u1u[k] : 0.f) - (rok ? u1u[k + 1] : 0.f))
                           : 0.f;
            float t1l = lok ? TAU * (u2w[k] - u2w[k + 1]
                                     + (up ? u3uw[k] : 0.f) - (down ? u3w[k] : 0.f))
                            : 0.f;

            float dv = t0u - (down ? t0c : 0.f) + t1l - (rok ? t1c : 0.f);
            float x  = (xoa[k] - dv + TAU * ya[k]) * INV_1PT;

            float rr0 = ro0[k] + t0c;
            float rr1 = ro1[k] + t1c;
            float s   = rr0 * rr0 + rr1 * rr1;
            float im  = fminf(TAU_LAM1 * rsqrtf(s), 1.0f);
            float r0  = rr0 - rr0 * im;
            float r1  = rr1 - rr1 * im;

            pxo[k] = 2.0f * x - xoa[k];
            p0o[k] = 2.0f * r0 - ro0[k];
            p1o[k] = 2.0f * r1 - ro1[k];
            xno[k] = xoa[k] + RHO * (x - xoa[k]);
            rn0[k] = ro0[k] + RHO * (r0 - ro0[k]);
            rn1[k] = ro1[k] + RHO * (r1 - ro1[k]);
        }
        st4(g_px[dst] + idx, pxo[0], pxo[1], pxo[2], pxo[3]);
        hst4(g_p0[dst] + idx, p0o[0], p0o[1], p0o[2], p0o[3]);
        hst4(g_p1[dst] + idx, p1o[0], p1o[1], p1o[2], p1o[3]);
        st4(x2 + idx, xno[0], xno[1], xno[2], xno[3]);
        st4(r2f + 2 * idx,     rn0[0], rn1[0], rn0[1], rn1[1]);
        st4(r2f + 2 * idx + 4, rn0[2], rn1[2], rn0[3], rn1[3]);
    }
}

// ---------------------------------------------------------------------------
// Final B_29: reads parity-src planes, writes u AoS float4 to d_out.
// ---------------------------------------------------------------------------
__global__ __launch_bounds__(256) void k_Bfinal(int src, float4* __restrict__ u2out) {
    int tid = threadIdx.x;
    int bid = blockIdx.x;
    int c   = bid >> 7;
    int rem = bid & 127;
    int bi  = rem >> 3;
    int bj  = rem & 7;
    int gi  = bi * 32 + (tid >> 4) * 2;
    int gj  = bj * 64 + (tid & 15) * 4;
    int idx0 = c * HW + gi * W + gj;

#if __CUDA_ARCH__ >= 900
    cudaGridDependencySynchronize();
#endif

#pragma unroll
    for (int qi = 0; qi < 2; ++qi) {
        int idx = idx0 + qi * W;
        float nu0[4], nu1[4], nu2[4], nu3[4];
        phaseB_compute(idx, src, nu0, nu1, nu2, nu3);
#pragma unroll
        for (int k = 0; k < 4; ++k)
            u2out[idx + k] = make_float4(nu0[k], nu1[k], nu2[k], nu3[k]);
    }
}

// ---------------------------------------------------------------------------
// PDL launches.
// ---------------------------------------------------------------------------
template <typename... Args>
static inline void launch_pdl(void (*kern)(Args...), int blocks, int threads,
                              Args... args) {
    cudaLaunchConfig_t cfg = {};
    cfg.gridDim  = dim3(blocks);
    cfg.blockDim = dim3(threads);
    cfg.stream   = 0;
    cudaLaunchAttribute attr[1];
    attr[0].id = cudaLaunchAttributeProgrammaticStreamSerialization;
    attr[0].val.programmaticStreamSerializationAllowed = 1;
    cfg.attrs = attr;
    cfg.numAttrs = 1;
    cudaLaunchKernelEx(&cfg, kern, args...);
}

extern "C" void kernel_launch(void* const* d_in, const int* in_sizes, int n_in,
                              void* d_out, int out_size) {
    const float* y = (const float*)d_in[0];
    float*  out = (float*)d_out;
    float*  x2  = out;
    float*  r2f = out + CHW;
    float4* u2o = (float4*)(out + 3 * CHW);

    const int threads = 256;
    const int blocks  = 384;

    k_setup<<<CHW / 4 / threads, threads>>>(y, x2, r2f);
    // F_it = B_{it-1} + A_it, it = 1..29; u^(k) and px_k live in buf[k&1].
    for (int it = 1; it < N_IT; ++it)
        launch_pdl(k_F, blocks, threads, (it - 1) & 1, x2, r2f, (const float*)y);
    // Final B_29: state parity (N_IT-1)&1 = 1.
    launch_pdl(k_Bfinal, blocks, threads, 1, u2o);
}

// round 17
// speedup vs baseline: 1.1666x; 1.1666x over previous
#include <cuda_runtime.h>
#include <cuda_fp16.h>

#define H 512
#define W 512
#define C 3
#define HW (H * W)
#define CHW (C * H * W)
#define N_IT 30

static constexpr float TAU      = (float)0.01;
static constexpr float LAM2     = (float)0.15;
static constexpr float RHO      = (float)1.99;
static constexpr float SIGMA    = (float)(1.0 / 0.01 / 72.0);
static constexpr float TAU_LAM1 = (float)(0.01 * 0.1);
static constexpr float INV_1PT  = (float)(1.0 / 1.01);

// Scratch: fp32 u planes + px, fp16 p0/p1 (|p| <= 3e-3, abs err ~1.5e-6)
__device__ float  g_u0[CHW], g_u1[CHW], g_u2p[CHW], g_u3[CHW];
__device__ float  g_px[CHW];
__device__ __half g_p0[CHW], g_p1[CHW];

__device__ __forceinline__ float4 ld4(const float* p) {
    return *reinterpret_cast<const float4*>(p);
}
__device__ __forceinline__ void st4(float* p, float a, float b, float c, float d) {
    *reinterpret_cast<float4*>(p) = make_float4(a, b, c, d);
}
__device__ __forceinline__ void hld4(const __half* p, float* o) {
    uint2 v = *reinterpret_cast<const uint2*>(p);
    float2 f0 = __half22float2(*reinterpret_cast<const __half2*>(&v.x));
    float2 f1 = __half22float2(*reinterpret_cast<const __half2*>(&v.y));
    o[0] = f0.x; o[1] = f0.y; o[2] = f1.x; o[3] = f1.y;
}
__device__ __forceinline__ float hld1(const __half* p) { return __half2float(*p); }
__device__ __forceinline__ void hst4(__half* p, float a, float b, float c, float d) {
    __half2 h0 = __floats2half2_rn(a, b);
    __half2 h1 = __floats2half2_rn(c, d);
    uint2 v;
    v.x = *reinterpret_cast<unsigned*>(&h0);
    v.y = *reinterpret_cast<unsigned*>(&h1);
    *reinterpret_cast<uint2*>(p) = v;
}

// ---------------------------------------------------------------------------
// Setup = init + trivial A_0: x2 = y, r2 = 0, u = 0, px = y, p0 = p1 = 0.
// ---------------------------------------------------------------------------
__global__ __launch_bounds__(256) void k_setup(const float* __restrict__ y,
                                               float* __restrict__ x2,
                                               float* __restrict__ r2f) {
    int t = blockIdx.x * blockDim.x + threadIdx.x;
    int idx = t * 4;
    float4 yv = ld4(y + idx);
    *reinterpret_cast<float4*>(x2 + idx)   = yv;
    *reinterpret_cast<float4*>(g_px + idx) = yv;
    st4(r2f + 2 * idx,     0.f, 0.f, 0.f, 0.f);
    st4(r2f + 2 * idx + 4, 0.f, 0.f, 0.f, 0.f);
    hst4(g_p0 + idx, 0.f, 0.f, 0.f, 0.f);
    hst4(g_p1 + idx, 0.f, 0.f, 0.f, 0.f);
    st4(g_u0 + idx, 0.f, 0.f, 0.f, 0.f);
    st4(g_u1 + idx, 0.f, 0.f, 0.f, 0.f);
    st4(g_u2p + idx, 0.f, 0.f, 0.f, 0.f);
    st4(g_u3 + idx, 0.f, 0.f, 0.f, 0.f);
}

// ---------------------------------------------------------------------------
// A compute+store for one quad given its pre-gathered u neighborhood.
// Bit-identical math to R15 phaseA.
// ---------------------------------------------------------------------------
__device__ __forceinline__ void compA(
    bool up, bool down, bool rowfirst, bool rowlast,
    const float* u0c, const float* u0u, const float* u0d,
    const float* u1c, const float* u1u,
    const float* u2w, const float* u3w, const float* u3uw,
    int idx, float* __restrict__ x2, float* __restrict__ r2f,
    const float* __restrict__ y)
{
    float4 xo4 = ld4(x2 + idx);
    float4 y4  = ld4(y + idx);
    float4 rA  = ld4(r2f + 2 * idx);
    float4 rB  = ld4(r2f + 2 * idx + 4);
    float xoa[4] = {xo4.x, xo4.y, xo4.z, xo4.w};
    float ya[4]  = {y4.x, y4.y, y4.z, y4.w};
    float ro0[4] = {rA.x, rA.z, rB.x, rB.z};
    float ro1[4] = {rA.y, rA.w, rB.y, rB.w};

    float pxo[4], p0o[4], p1o[4], xno[4], rn0[4], rn1[4];
#pragma unroll
    for (int k = 0; k < 4; ++k) {
        bool lok = (k > 0) || !rowfirst;          // j >= 1
        bool rok = (k < 3) || !rowlast;           // j < W-1

        float t0c = TAU * (u0c[k] - (down ? u0d[k] : 0.f)
                           + (lok ? u1c[k] : 0.f) - (rok ? u1c[k + 1] : 0.f));
        float t1c = TAU * (u2w[k + 1] - (rok ? u2w[k + 2] : 0.f)
                           + (up ? u3uw[k + 1] : 0.f) - (down ? u3w[k + 1] : 0.f));
        float t0u = up ? TAU * (u0u[k] - u0c[k]
                                + (lok ? u1u[k] : 0.f) - (rok ? u1u[k + 1] : 0.f))
                       : 0.f;
        float t1l = lok ? TAU * (u2w[k] - u2w[k + 1]
                                 + (up ? u3uw[k] : 0.f) - (down ? u3w[k] : 0.f))
                        : 0.f;

        float dv = t0u - (down ? t0c : 0.f) + t1l - (rok ? t1c : 0.f);
        float x  = (xoa[k] - dv + TAU * ya[k]) * INV_1PT;

        float rr0 = ro0[k] + t0c;
        float rr1 = ro1[k] + t1c;
        float s   = rr0 * rr0 + rr1 * rr1;
        float im  = fminf(TAU_LAM1 * rsqrtf(s), 1.0f);
        float r0  = rr0 - rr0 * im;
        float r1  = rr1 - rr1 * im;

        pxo[k] = 2.0f * x - xoa[k];
        p0o[k] = 2.0f * r0 - ro0[k];
        p1o[k] = 2.0f * r1 - ro1[k];
        xno[k] = xoa[k] + RHO * (x - xoa[k]);
        rn0[k] = ro0[k] + RHO * (r0 - ro0[k]);
        rn1[k] = ro1[k] + RHO * (r1 - ro1[k]);
    }
    st4(g_px + idx, pxo[0], pxo[1], pxo[2], pxo[3]);
    hst4(g_p0 + idx, p0o[0], p0o[1], p0o[2], p0o[3]);
    hst4(g_p1 + idx, p1o[0], p1o[1], p1o[2], p1o[3]);
    st4(x2 + idx, xno[0], xno[1], xno[2], xno[3]);
    st4(r2f + 2 * idx,     rn0[0], rn1[0], rn0[1], rn1[1]);
    st4(r2f + 2 * idx + 4, rn0[2], rn1[2], rn0[3], rn1[3]);
}

// ---------------------------------------------------------------------------
// B compute+store for one quad given its pre-gathered px/p0/p1 neighborhood.
// Bit-identical math to R15 phaseB.
// ---------------------------------------------------------------------------
__device__ __forceinline__ void compB(
    bool up, bool down, bool rowfirst, bool rowlast,
    const float* pxa /*6*/, const float* pxda /*6*/, const float* pxua /*4*/,
    const float* p0w /*5*/, const float* p0ua /*4*/,
    const float* p1w /*5*/, const float* p1da /*4*/,
    int idx, float4* __restrict__ u2out, int last)
{
    float4 u0c = ld4(g_u0 + idx);
    float4 u1c = ld4(g_u1 + idx);
    float4 u2c = ld4(g_u2p + idx);
    float4 u3c = ld4(g_u3 + idx);
    float uo0[4] = {u0c.x, u0c.y, u0c.z, u0c.w};
    float uo1[4] = {u1c.x, u1c.y, u1c.z, u1c.w};
    float uo2[4] = {u2c.x, u2c.y, u2c.z, u2c.w};
    float uo3[4] = {u3c.x, u3c.y, u3c.z, u3c.w};

    float nu0[4], nu1[4], nu2[4], nu3[4];
#pragma unroll
    for (int k = 0; k < 4; ++k) {
        int kc = k + 1;
        bool lok = (k > 0) || !rowfirst;
        bool rok = (k < 3) || !rowlast;

        float q0c = (down ? (pxda[kc] - pxa[kc]) : 0.f) - p0w[k + 1];
        float q0u = up  ? ((pxa[kc] - pxua[k]) - p0ua[k]) : 0.f;
        float q0l = lok ? ((down ? (pxda[kc - 1] - pxa[kc - 1]) : 0.f) - p0w[k]) : 0.f;
        float q1c = (rok ? (pxa[kc + 1] - pxa[kc]) : 0.f) - p1w[k + 1];
        float q1l = lok ? ((pxa[kc] - pxa[kc - 1]) - p1w[k]) : 0.f;
        float q1d = down ? ((rok ? (pxda[kc + 1] - pxda[kc]) : 0.f) - p1da[k]) : 0.f;

        float e0 = q0c - q0u;
        float e1 = lok ? (q0c - q0l) : 0.f;
        float e2 = q1c - q1l;
        float e3 = down ? (q1d - q1c) : 0.f;

        float un0 = uo0[k] + SIGMA * e0;
        float un1 = uo1[k] + SIGMA * e1;
        float un2 = uo2[k] + SIGMA * e2;
        float un3 = uo3[k] + SIGMA * e3;

        float s  = un0 * un0 + un1 * un1 + un2 * un2 + un3 * un3;
        float im = fminf(LAM2 * rsqrtf(s), 1.0f);

        nu0[k] = uo0[k] + RHO * (un0 * im - uo0[k]);
        nu1[k] = uo1[k] + RHO * (un1 * im - uo1[k]);
        nu2[k] = uo2[k] + RHO * (un2 * im - uo2[k]);
        nu3[k] = uo3[k] + RHO * (un3 * im - uo3[k]);
    }

    if (last) {
#pragma unroll
        for (int k = 0; k < 4; ++k)
            u2out[idx + k] = make_float4(nu0[k], nu1[k], nu2[k], nu3[k]);
    } else {
        st4(g_u0 + idx, nu0[0], nu0[1], nu0[2], nu0[3]);
        st4(g_u1 + idx, nu1[0], nu1[1], nu1[2], nu1[3]);
        st4(g_u2p + idx, nu2[0], nu2[1], nu2[2], nu2[3]);
        st4(g_u3 + idx, nu3[0], nu3[1], nu3[2], nu3[3]);
    }
}

// ---------------------------------------------------------------------------
// k_A: row-pair per thread with UNIONED u loads (rows gi-1..gi+2).
// quad0 (row gi): up=gi>=1, down=true (gi<=510). quad1: up=true, down=gi+2<H.
// ---------------------------------------------------------------------------
__global__ __launch_bounds__(256) void k_A(float* __restrict__ x2,
                                           float* __restrict__ r2f,
                                           const float* __restrict__ y) {
    int tid = threadIdx.x, bid = blockIdx.x;
    int c = bid >> 7, rem = bid & 127;
    int bi = rem >> 3, bj = rem & 7;
    int gi = bi * 32 + (tid >> 4) * 2;
    int gj = bj * 64 + (tid & 15) * 4;
    int idx = c * HW + gi * W + gj;
    bool up0 = (gi >= 1);
    bool dn1 = (gi + 2 < H);
    bool rowfirst = (gj == 0), rowlast = (gj + 4 == W);

#if __CUDA_ARCH__ >= 900
    cudaGridDependencySynchronize();
#endif

    const float4 Z = make_float4(0, 0, 0, 0);
    // u0: rows gi-1, gi, gi+1, gi+2
    float4 u0m = up0 ? ld4(g_u0 + idx - W) : Z;
    float4 u0a = ld4(g_u0 + idx);
    float4 u0b = ld4(g_u0 + idx + W);
    float4 u0c2 = dn1 ? ld4(g_u0 + idx + 2 * W) : Z;
    // u1: rows gi-1, gi, gi+1 (float4 + right scalar)
    float4 u1m4 = up0 ? ld4(g_u1 + idx - W) : Z;
    float  u1mr = (up0 && !rowlast) ? g_u1[idx - W + 4] : 0.f;
    float4 u1a4 = ld4(g_u1 + idx);
    float  u1ar = rowlast ? 0.f : g_u1[idx + 4];
    float4 u1b4 = ld4(g_u1 + idx + W);
    float  u1br = rowlast ? 0.f : g_u1[idx + W + 4];
    // u2: rows gi, gi+1 (left + float4 + right)
    float  u2al = rowfirst ? 0.f : g_u2p[idx - 1];
    float4 u2a4 = ld4(g_u2p + idx);
    float  u2ar = rowlast ? 0.f : g_u2p[idx + 4];
    float  u2bl = rowfirst ? 0.f : g_u2p[idx + W - 1];
    float4 u2b4 = ld4(g_u2p + idx + W);
    float  u2br = rowlast ? 0.f : g_u2p[idx + W + 4];
    // u3: rows gi-1, gi, gi+1 (left + float4)
    float  u3ml = (up0 && !rowfirst) ? g_u3[idx - W - 1] : 0.f;
    float4 u3m4 = up0 ? ld4(g_u3 + idx - W) : Z;
    float  u3al = rowfirst ? 0.f : g_u3[idx - 1];
    float4 u3a4 = ld4(g_u3 + idx);
    float  u3bl = rowfirst ? 0.f : g_u3[idx + W - 1];
    float4 u3b4 = ld4(g_u3 + idx + W);

    {   // quad0 @ row gi
        float u0c[4] = {u0a.x, u0a.y, u0a.z, u0a.w};
        float u0u[4] = {u0m.x, u0m.y, u0m.z, u0m.w};
        float u0d[4] = {u0b.x, u0b.y, u0b.z, u0b.w};
        float u1c[5] = {u1a4.x, u1a4.y, u1a4.z, u1a4.w, u1ar};
        float u1u[5] = {u1m4.x, u1m4.y, u1m4.z, u1m4.w, u1mr};
        float u2w[6] = {u2al, u2a4.x, u2a4.y, u2a4.z, u2a4.w, u2ar};
        float u3w[5] = {u3al, u3a4.x, u3a4.y, u3a4.z, u3a4.w};
        float u3uw[5]= {u3ml, u3m4.x, u3m4.y, u3m4.z, u3m4.w};
        compA(up0, true, rowfirst, rowlast,
              u0c, u0u, u0d, u1c, u1u, u2w, u3w, u3uw, idx, x2, r2f, y);
    }
    {   // quad1 @ row gi+1
        float u0c[4] = {u0b.x, u0b.y, u0b.z, u0b.w};
        float u0u[4] = {u0a.x, u0a.y, u0a.z, u0a.w};
        float u0d[4] = {u0c2.x, u0c2.y, u0c2.z, u0c2.w};
        float u1c[5] = {u1b4.x, u1b4.y, u1b4.z, u1b4.w, u1br};
        float u1u[5] = {u1a4.x, u1a4.y, u1a4.z, u1a4.w, u1ar};
        float u2w[6] = {u2bl, u2b4.x, u2b4.y, u2b4.z, u2b4.w, u2br};
        float u3w[5] = {u3bl, u3b4.x, u3b4.y, u3b4.z, u3b4.w};
        float u3uw[5]= {u3al, u3a4.x, u3a4.y, u3a4.z, u3a4.w};
        compA(true, dn1, rowfirst, rowlast,
              u0c, u0u, u0d, u1c, u1u, u2w, u3w, u3uw, idx + W, x2, r2f, y);
    }
}

// ---------------------------------------------------------------------------
// k_B: row-pair per thread with UNIONED px/p0/p1 loads (rows gi-1..gi+2).
// ---------------------------------------------------------------------------
__global__ __launch_bounds__(256) void k_B(float4* __restrict__ u2out, int last) {
    int tid = threadIdx.x, bid = blockIdx.x;
    int c = bid >> 7, rem = bid & 127;
    int bi = rem >> 3, bj = rem & 7;
    int gi = bi * 32 + (tid >> 4) * 2;
    int gj = bj * 64 + (tid & 15) * 4;
    int idx = c * HW + gi * W + gj;
    bool up0 = (gi >= 1);
    bool dn1 = (gi + 2 < H);
    bool rowfirst = (gj == 0), rowlast = (gj + 4 == W);

#if __CUDA_ARCH__ >= 900
    cudaGridDependencySynchronize();
#endif

    const float4 Z = make_float4(0, 0, 0, 0);
    // px rows: gi-1 (center only), gi, gi+1, gi+2 (l/c/r)
    float4 pxm  = up0 ? ld4(g_px + idx - W) : Z;
    float  pxal = rowfirst ? 0.f : g_px[idx - 1];
    float4 pxa4 = ld4(g_px + idx);
    float  pxar = rowlast ? 0.f : g_px[idx + 4];
    float  pxbl = rowfirst ? 0.f : g_px[idx + W - 1];
    float4 pxb4 = ld4(g_px + idx + W);
    float  pxbr = rowlast ? 0.f : g_px[idx + W + 4];
    float  pxcl = (dn1 && !rowfirst) ? g_px[idx + 2 * W - 1] : 0.f;
    float4 pxc4 = dn1 ? ld4(g_px + idx + 2 * W) : Z;
    float  pxcr = (dn1 && !rowlast) ? g_px[idx + 2 * W + 4] : 0.f;

    // p0 rows: gi-1 (c), gi (l,c), gi+1 (l,c)
    float p0m[4] = {0, 0, 0, 0};
    if (up0) hld4(g_p0 + idx - W, p0m);
    float p0al = rowfirst ? 0.f : hld1(g_p0 + idx - 1);
    float p0a[4]; hld4(g_p0 + idx, p0a);
    float p0bl = rowfirst ? 0.f : hld1(g_p0 + idx + W - 1);
    float p0b[4]; hld4(g_p0 + idx + W, p0b);

    // p1 rows: gi (l,c), gi+1 (l,c), gi+2 (c)
    float p1al = rowfirst ? 0.f : hld1(g_p1 + idx - 1);
    float p1a[4]; hld4(g_p1 + idx, p1a);
    float p1bl = rowfirst ? 0.f : hld1(g_p1 + idx + W - 1);
    float p1b[4]; hld4(g_p1 + idx + W, p1b);
    float p1c[4] = {0, 0, 0, 0};
    if (dn1) hld4(g_p1 + idx + 2 * W, p1c);

    {   // quad0 @ row gi
        float pxa[6]  = {pxal, pxa4.x, pxa4.y, pxa4.z, pxa4.w, pxar};
        float pxda[6] = {pxbl, pxb4.x, pxb4.y, pxb4.z, pxb4.w, pxbr};
        float pxua[4] = {pxm.x, pxm.y, pxm.z, pxm.w};
        float p0w[5]  = {p0al, p0a[0], p0a[1], p0a[2], p0a[3]};
        float p1w[5]  = {p1al, p1a[0], p1a[1], p1a[2], p1a[3]};
        compB(up0, true, rowfirst, rowlast,
              pxa, pxda, pxua, p0w, p0m, p1w, p1b, idx, u2out, last);
    }
    {   // quad1 @ row gi+1
        float pxa[6]  = {pxbl, pxb4.x, pxb4.y, pxb4.z, pxb4.w, pxbr};
        float pxda[6] = {pxcl, pxc4.x, pxc4.y, pxc4.z, pxc4.w, pxcr};
        float pxua[4] = {pxa4.x, pxa4.y, pxa4.z, pxa4.w};
        float p0w[5]  = {p0bl, p0b[0], p0b[1], p0b[2], p0b[3]};
        float p1w[5]  = {p1bl, p1b[0], p1b[1], p1b[2], p1b[3]};
        compB(true, dn1, rowfirst, rowlast,
              pxa, pxda, pxua, p0w, p0a, p1w, p1c, idx + W, u2out, last);
    }
}

// ---------------------------------------------------------------------------
// PDL launches.
// ---------------------------------------------------------------------------
template <typename... Args>
static inline void launch_pdl(void (*kern)(Args...), int blocks, int threads,
                              Args... args) {
    cudaLaunchConfig_t cfg = {};
    cfg.gridDim  = dim3(blocks);
    cfg.blockDim = dim3(threads);
    cfg.stream   = 0;
    cudaLaunchAttribute attr[1];
    attr[0].id = cudaLaunchAttributeProgrammaticStreamSerialization;
    attr[0].val.programmaticStreamSerializationAllowed = 1;
    cfg.attrs = attr;
    cfg.numAttrs = 1;
    cudaLaunchKernelEx(&cfg, kern, args...);
}

extern "C" void kernel_launch(void* const* d_in, const int* in_sizes, int n_in,
                              void* d_out, int out_size) {
    const float* y = (const float*)d_in[0];
    float*  out = (float*)d_out;
    float*  x2  = out;
    float*  r2f = out + CHW;
    float4* u2o = (float4*)(out + 3 * CHW);

    const int threads = 256;
    const int blocks  = 384;   // 16 i-tiles x 8 j-tiles x 3 channels

    k_setup<<<CHW / 4 / threads, threads>>>(y, x2, r2f);
    launch_pdl(k_B, blocks, threads, u2o, 0);          // B_0
    for (int it = 1; it < N_IT; ++it) {
        launch_pdl(k_A, blocks, threads, x2, r2f, (const float*)y);
        launch_pdl(k_B, blocks, threads, u2o, it == N_IT - 1 ? 1 : 0);
    }
}